// round 1
// baseline (speedup 1.0000x reference)
#include <cuda_runtime.h>

#define BATCH 2048
#define CELL 512
#define KDIM 30
#define LPAD 1024
#define VDIM 80
#define NTHREADS 256

__global__ __launch_bounds__(NTHREADS) void window_kernel(
    const float* __restrict__ x,          // [B, CELL]
    const float* __restrict__ kappa_old,  // [B, K]
    const float4* __restrict__ onehots,   // [B, L, V] as float4
    const float* __restrict__ text_lens,  // [B, 1]
    const float* __restrict__ W,          // [3K, CELL]
    const float* __restrict__ bias,       // [3K]
    float* __restrict__ out_w,            // [B, V]
    float* __restrict__ out_kappa,        // [B, K]
    float* __restrict__ out_phi)          // [B, L+1]
{
    __shared__ float sx[CELL];
    __shared__ float s_alpha[KDIM];
    __shared__ float s_beta[KDIM];
    __shared__ float s_kappa[KDIM];
    __shared__ float s_phi[LPAD];
    __shared__ float s_w[VDIM];

    const int bid = blockIdx.x;
    const int tid = threadIdx.x;
    const int wid = tid >> 5;
    const int lane = tid & 31;

    // Load x row into shared
    #pragma unroll
    for (int i = tid; i < CELL; i += NTHREADS)
        sx[i] = x[(size_t)bid * CELL + i];
    if (tid < VDIM) s_w[tid] = 0.0f;
    __syncthreads();

    // 90 dot products over 512: one warp per output, round-robin
    for (int o = wid; o < 3 * KDIM; o += NTHREADS / 32) {
        const float* wrow = W + (size_t)o * CELL;
        float acc = 0.0f;
        #pragma unroll 4
        for (int i = lane; i < CELL; i += 32)
            acc = fmaf(wrow[i], sx[i], acc);
        #pragma unroll
        for (int off = 16; off; off >>= 1)
            acc += __shfl_xor_sync(0xffffffffu, acc, off);
        if (lane == 0) {
            float p = __expf(acc + bias[o]);
            if (o < KDIM) {
                s_alpha[o] = p;
            } else if (o < 2 * KDIM) {
                s_beta[o - KDIM] = p;
            } else {
                int k = o - 2 * KDIM;
                float kp = kappa_old[(size_t)bid * KDIM + k] + p;
                s_kappa[k] = kp;
                out_kappa[(size_t)bid * KDIM + k] = kp;
            }
        }
    }
    __syncthreads();

    const float scale = (float)LPAD / text_lens[bid];

    // phi[l] for l in [0, LPAD]
    for (int l = tid; l <= LPAD; l += NTHREADS) {
        const float fl = (float)l;
        float acc = 0.0f;
        #pragma unroll
        for (int k = 0; k < KDIM; k++) {
            float d = s_kappa[k] - fl;
            acc = fmaf(s_alpha[k], __expf(-s_beta[k] * d * d), acc);
        }
        float ph = acc * scale;
        out_phi[(size_t)bid * (LPAD + 1) + l] = ph;
        if (l < LPAD) s_phi[l] = ph;
    }
    __syncthreads();

    // w[v] = sum_l phi[l] * onehots[l][v]  — streaming float4 read,
    // sparse shared atomics (one-hot: ~1 nonzero per row of 80)
    const float4* oh = onehots + (size_t)bid * (LPAD * VDIM / 4);
    const int n4 = LPAD * VDIM / 4;  // 20480
    #pragma unroll 4
    for (int i = tid; i < n4; i += NTHREADS) {
        float4 v4 = oh[i];
        int e = i * 4;
        int l = e / VDIM;        // VDIM divisible by 4 -> whole float4 in one l
        int vb = e - l * VDIM;
        float ph = s_phi[l];
        if (v4.x != 0.0f) atomicAdd(&s_w[vb + 0], ph * v4.x);
        if (v4.y != 0.0f) atomicAdd(&s_w[vb + 1], ph * v4.y);
        if (v4.z != 0.0f) atomicAdd(&s_w[vb + 2], ph * v4.z);
        if (v4.w != 0.0f) atomicAdd(&s_w[vb + 3], ph * v4.w);
    }
    __syncthreads();

    if (tid < VDIM) out_w[(size_t)bid * VDIM + tid] = s_w[tid];
}

extern "C" void kernel_launch(void* const* d_in, const int* in_sizes, int n_in,
                              void* d_out, int out_size) {
    const float* x         = (const float*)d_in[0];
    const float* kappa_old = (const float*)d_in[1];
    const float4* onehots  = (const float4*)d_in[2];
    const float* text_lens = (const float*)d_in[3];
    const float* W         = (const float*)d_in[4];
    const float* bias      = (const float*)d_in[5];

    float* out = (float*)d_out;
    float* out_w     = out;                                  // [B, V]
    float* out_kappa = out + (size_t)BATCH * VDIM;           // [B, K]
    float* out_phi   = out + (size_t)BATCH * (VDIM + KDIM);  // [B, L+1]

    window_kernel<<<BATCH, NTHREADS>>>(x, kappa_old, onehots, text_lens, W, bias,
                                       out_w, out_kappa, out_phi);
}

// round 2
// speedup vs baseline: 1.4937x; 1.4937x over previous
#include <cuda_runtime.h>

#define BATCH 2048
#define CELL 512
#define KDIM 30
#define LPAD 1024
#define VDIM 80

// ---------------------------------------------------------------------------
// Kernel 1: params (alpha, beta, kappa) + phi.  Register-heavy but tiny.
// ---------------------------------------------------------------------------
__global__ __launch_bounds__(256) void params_phi_kernel(
    const float* __restrict__ x,          // [B, CELL]
    const float* __restrict__ kappa_old,  // [B, K]
    const float* __restrict__ text_lens,  // [B, 1]
    const float* __restrict__ W,          // [3K, CELL]
    const float* __restrict__ bias,       // [3K]
    float* __restrict__ out_kappa,        // [B, K]
    float* __restrict__ out_phi)          // [B, L+1]
{
    __shared__ float sx[CELL];
    __shared__ float s_alpha[KDIM];
    __shared__ float s_beta[KDIM];
    __shared__ float s_kappa[KDIM];

    const int bid = blockIdx.x;
    const int tid = threadIdx.x;
    const int wid = tid >> 5;
    const int lane = tid & 31;

    #pragma unroll
    for (int i = tid; i < CELL; i += 256)
        sx[i] = x[(size_t)bid * CELL + i];
    __syncthreads();

    // 90 dot products over 512: one warp per output, round-robin
    for (int o = wid; o < 3 * KDIM; o += 8) {
        const float* wrow = W + (size_t)o * CELL;
        float acc = 0.0f;
        #pragma unroll 4
        for (int i = lane; i < CELL; i += 32)
            acc = fmaf(wrow[i], sx[i], acc);
        #pragma unroll
        for (int off = 16; off; off >>= 1)
            acc += __shfl_xor_sync(0xffffffffu, acc, off);
        if (lane == 0) {
            float p = __expf(acc + bias[o]);
            if (o < KDIM) {
                s_alpha[o] = p;
            } else if (o < 2 * KDIM) {
                s_beta[o - KDIM] = p;
            } else {
                int k = o - 2 * KDIM;
                float kp = kappa_old[(size_t)bid * KDIM + k] + p;
                s_kappa[k] = kp;
                out_kappa[(size_t)bid * KDIM + k] = kp;
            }
        }
    }
    __syncthreads();

    const float scale = (float)LPAD / text_lens[bid];

    for (int l = tid; l <= LPAD; l += 256) {
        const float fl = (float)l;
        float acc = 0.0f;
        #pragma unroll
        for (int k = 0; k < KDIM; k++) {
            float d = s_kappa[k] - fl;
            acc = fmaf(s_alpha[k], __expf(-s_beta[k] * d * d), acc);
        }
        out_phi[(size_t)bid * (LPAD + 1) + l] = acc * scale;
    }
}

// ---------------------------------------------------------------------------
// Kernel 2: w[b,v] = sum_l phi[b,l] * onehots[b,l,v].  Pure streaming.
// Per thread: i = tid + 256*j, j = 0..79.  Column base (4i mod 80) has
// period 5 in j; row l advances by exactly +64 per 5-step group.
// -> 5 float4 register accumulators, branchless inner loop.
// ---------------------------------------------------------------------------
__global__ __launch_bounds__(256) void wsum_kernel(
    const float4* __restrict__ onehots,   // [B, L*V/4]
    const float* __restrict__ phi,        // [B, L+1]
    float* __restrict__ out_w)            // [B, V]
{
    __shared__ float s_phi[LPAD];
    __shared__ float s_w[VDIM];

    const int bid = blockIdx.x;
    const int tid = threadIdx.x;

    #pragma unroll
    for (int i = tid; i < LPAD; i += 256)
        s_phi[i] = phi[(size_t)bid * (LPAD + 1) + i];
    if (tid < VDIM) s_w[tid] = 0.0f;
    __syncthreads();

    const float4* oh = onehots + (size_t)bid * (LPAD * VDIM / 4);

    float4 acc[5];
    int l0[5], cb[5];
    #pragma unroll
    for (int m = 0; m < 5; m++) {
        int e0 = 4 * tid + 1024 * m;
        l0[m] = e0 / VDIM;
        cb[m] = e0 % VDIM;
        acc[m] = make_float4(0.f, 0.f, 0.f, 0.f);
    }

    #pragma unroll 2
    for (int g = 0; g < 16; g++) {
        #pragma unroll
        for (int m = 0; m < 5; m++) {
            float4 v4 = __ldcs(&oh[tid + 256 * (m + 5 * g)]);
            float ph = s_phi[l0[m] + 64 * g];
            acc[m].x = fmaf(ph, v4.x, acc[m].x);
            acc[m].y = fmaf(ph, v4.y, acc[m].y);
            acc[m].z = fmaf(ph, v4.z, acc[m].z);
            acc[m].w = fmaf(ph, v4.w, acc[m].w);
        }
    }
    __syncthreads();

    #pragma unroll
    for (int m = 0; m < 5; m++) {
        atomicAdd(&s_w[cb[m] + 0], acc[m].x);
        atomicAdd(&s_w[cb[m] + 1], acc[m].y);
        atomicAdd(&s_w[cb[m] + 2], acc[m].z);
        atomicAdd(&s_w[cb[m] + 3], acc[m].w);
    }
    __syncthreads();

    if (tid < VDIM) out_w[(size_t)bid * VDIM + tid] = s_w[tid];
}

extern "C" void kernel_launch(void* const* d_in, const int* in_sizes, int n_in,
                              void* d_out, int out_size) {
    const float* x         = (const float*)d_in[0];
    const float* kappa_old = (const float*)d_in[1];
    const float4* onehots  = (const float4*)d_in[2];
    const float* text_lens = (const float*)d_in[3];
    const float* W         = (const float*)d_in[4];
    const float* bias      = (const float*)d_in[5];

    float* out = (float*)d_out;
    float* out_w     = out;                                  // [B, V]
    float* out_kappa = out + (size_t)BATCH * VDIM;           // [B, K]
    float* out_phi   = out + (size_t)BATCH * (VDIM + KDIM);  // [B, L+1]

    params_phi_kernel<<<BATCH, 256>>>(x, kappa_old, text_lens, W, bias,
                                      out_kappa, out_phi);
    wsum_kernel<<<BATCH, 256>>>(onehots, out_phi, out_w);
}